// round 9
// baseline (speedup 1.0000x reference)
#include <cuda_runtime.h>
#include <cuda_bf16.h>
#include <math.h>
#include <stdint.h>

// ---------------- problem constants ----------------
#define BS      2
#define NQ      40000
#define NV      40000
#define EMBED   256
#define HEADS   8
#define POINTS  4
#define HEAD_DIM 32
#define SH      200
#define SW      200
#define MROWS   (BS * NQ)      // 80000

// ---------------- device scratch ----------------
__device__ float g_v   [(size_t)BS * NV * EMBED];        // projected value (fp32)
__device__ float g_oa  [(size_t)BS * NQ * 96];           // fused [off(64) | attn(32)]
__device__ float g_tmp [(size_t)BS * NQ * EMBED];
__device__ float g_boa [96];
// transposed + split weights: [N][K] bf16
__device__ __nv_bfloat16 g_Wv_hi [256 * 256], g_Wv_lo [256 * 256];
__device__ __nv_bfloat16 g_Wo_hi [256 * 256], g_Wo_lo [256 * 256];
__device__ __nv_bfloat16 g_Woa_hi[ 96 * 256], g_Woa_lo[ 96 * 256];

// ---------------- warp mma / ldmatrix / cp.async helpers ----------------
__device__ __forceinline__ void mma_bf16(float* d, const uint32_t* a, const uint32_t* b) {
    asm volatile(
        "mma.sync.aligned.m16n8k16.row.col.f32.bf16.bf16.f32 "
        "{%0,%1,%2,%3}, {%4,%5,%6,%7}, {%8,%9}, {%0,%1,%2,%3};"
        : "+f"(d[0]), "+f"(d[1]), "+f"(d[2]), "+f"(d[3])
        : "r"(a[0]), "r"(a[1]), "r"(a[2]), "r"(a[3]), "r"(b[0]), "r"(b[1]));
}
__device__ __forceinline__ void ldsm_x4(uint32_t& r0, uint32_t& r1, uint32_t& r2, uint32_t& r3,
                                        uint32_t addr) {
    asm volatile("ldmatrix.sync.aligned.m8n8.x4.shared.b16 {%0,%1,%2,%3}, [%4];"
                 : "=r"(r0), "=r"(r1), "=r"(r2), "=r"(r3) : "r"(addr));
}
__device__ __forceinline__ void ldsm_x2(uint32_t& r0, uint32_t& r1, uint32_t addr) {
    asm volatile("ldmatrix.sync.aligned.m8n8.x2.shared.b16 {%0,%1}, [%2];"
                 : "=r"(r0), "=r"(r1) : "r"(addr));
}
__device__ __forceinline__ void cp_async16(uint32_t dst, const void* src) {
    asm volatile("cp.async.cg.shared.global [%0], [%1], 16;" :: "r"(dst), "l"(src) : "memory");
}
__device__ __forceinline__ uint32_t cvt_bf16x2(float hi, float lo) {
    uint32_t r;
    asm("cvt.rn.bf16x2.f32 %0, %1, %2;" : "=r"(r) : "f"(hi), "f"(lo));
    return r;
}

// ---------------- weight transpose + bf16 split ----------------
__global__ void convert_w_kernel(const float* __restrict__ W,
                                 __nv_bfloat16* __restrict__ hi,
                                 __nv_bfloat16* __restrict__ lo, int N)
{
    int idx = blockIdx.x * 256 + threadIdx.x;
    if (idx >= N * 256) return;
    int n = idx >> 8, k = idx & 255;
    float v = W[k * N + n];
    __nv_bfloat16 h = __float2bfloat16(v);
    hi[idx] = h;
    lo[idx] = __float2bfloat16(v - __bfloat162float(h));
}

__global__ void convert_oa_kernel(const float* __restrict__ Woff, const float* __restrict__ boff,
                                  const float* __restrict__ Wattn, const float* __restrict__ battn,
                                  __nv_bfloat16* __restrict__ hi, __nv_bfloat16* __restrict__ lo,
                                  float* __restrict__ bcomb)
{
    int idx = blockIdx.x * 256 + threadIdx.x;
    if (idx >= 96 * 256) return;
    int n = idx >> 8, k = idx & 255;
    float v = (n < 64) ? Woff[k * 64 + n] : Wattn[k * 32 + (n - 64)];
    __nv_bfloat16 h = __float2bfloat16(v);
    hi[idx] = h;
    lo[idx] = __float2bfloat16(v - __bfloat162float(h));
    if (idx < 96) bcomb[idx] = (idx < 64) ? boff[idx] : battn[idx - 64];
}

// ---------------- split-bf16 HMMA GEMM v5: cp.async B double-buffer ----------------
// CTA tile: 128 x BN. gridDim.y splits total N. 8 warps, warp tile 64 x (BN/4).
template<int BN, bool RES>
__global__ void __launch_bounds__(256, 2)
mma_gemm_kernel(const float* __restrict__ A,
                const __nv_bfloat16* __restrict__ Bt_hi,
                const __nv_bfloat16* __restrict__ Bt_lo,
                const float* __restrict__ bias,
                const float* __restrict__ res,
                float* __restrict__ C, int ldC)
{
    constexpr int K = 256, BK = 64, BM = 128;
    constexpr int WN  = 4;
    constexpr int WTN = BN / WN;
    constexpr int MT  = 4;
    constexpr int NTI = WTN / 8;
    constexpr int NPAIR = NTI / 2;
    constexpr int AST = 144;
    constexpr int A_H = 0;
    constexpr int A_L = BM * AST;
    constexpr int B0  = 2 * BM * AST;         // base of B buffers
    constexpr int BPL = BN * AST;             // one B plane
    constexpr int BUFSZ = 2 * BPL;            // hi+lo per buffer

    extern __shared__ char sm[];
    const uint32_t smBase = (uint32_t)__cvta_generic_to_shared(sm);

    const int tid  = threadIdx.x;
    const int wid  = tid >> 5;
    const int lane = tid & 31;
    const int g    = lane >> 2;
    const int c    = lane & 3;
    const int wm   = wid / WN;
    const int wn   = wid % WN;
    const int wmBase = wm * 64;
    const int wnBase = wn * WTN;
    const int bm   = blockIdx.x;
    const int nOff = blockIdx.y * BN;

    float acc[MT][NTI][4];
#pragma unroll
    for (int i = 0; i < MT; i++)
#pragma unroll
        for (int j = 0; j < NTI; j++)
#pragma unroll
            for (int q = 0; q < 4; q++) acc[i][j][q] = 0.f;

    const int aRow = wmBase + (lane & 15);
    const int aKs  = (lane >> 4) * 16;
    const int bRow = wnBase + ((lane >> 4) << 3) + (lane & 7);
    const int bKs  = ((lane >> 3) & 1) * 16;
    const uint32_t aHiB = smBase + (uint32_t)(A_H + aRow * AST + aKs);
    const uint32_t aLoB = aHiB + (uint32_t)(A_L - A_H);
    const uint32_t bBase = smBase + (uint32_t)(B0 + bRow * AST + bKs);

    // ---- B copy via cp.async (pure 16B copies of pre-split planes) ----
    auto copyB = [&](int it, int buf) {
        const int k0 = it * BK;
        const uint32_t d0 = smBase + (uint32_t)(B0 + buf * BUFSZ);
#pragma unroll
        for (int f = tid; f < BN * 8; f += 256) {
            const int n = f >> 3, cu = f & 7;
            cp_async16(d0 + (uint32_t)(n * AST + cu * 16),
                       &Bt_hi[(nOff + n) * K + k0 + cu * 8]);
            cp_async16(d0 + (uint32_t)(BPL + n * AST + cu * 16),
                       &Bt_lo[(nOff + n) * K + k0 + cu * 8]);
        }
        asm volatile("cp.async.commit_group;" ::: "memory");
    };

    copyB(0, 0);

#pragma unroll
    for (int it = 0; it < K / BK; it++) {
        const int k0 = it * BK;
        // ---- fill A tile: 128 rows x 64 fp32 -> bf16 hi/lo (packed cvt) ----
#pragma unroll
        for (int f = tid; f < BM * 16; f += 256) {
            const int r = f >> 4, c4 = f & 15;
            float4 a = *reinterpret_cast<const float4*>(
                &A[(size_t)(bm * BM + r) * K + k0 + c4 * 4]);
            uint32_t hA = cvt_bf16x2(a.y, a.x);
            uint32_t hB = cvt_bf16x2(a.w, a.z);
            float f0 = __uint_as_float(hA << 16);
            float f1 = __uint_as_float(hA & 0xffff0000u);
            float f2 = __uint_as_float(hB << 16);
            float f3 = __uint_as_float(hB & 0xffff0000u);
            uint32_t lA = cvt_bf16x2(a.y - f1, a.x - f0);
            uint32_t lB = cvt_bf16x2(a.w - f3, a.z - f2);
            uint2 vh; vh.x = hA; vh.y = hB;
            uint2 vl; vl.x = lA; vl.y = lB;
            *reinterpret_cast<uint2*>(sm + A_H + r * AST + c4 * 8) = vh;
            *reinterpret_cast<uint2*>(sm + A_L + r * AST + c4 * 8) = vl;
        }
        // prefetch next B chunk into the other buffer, then wait for current
        if (it < K / BK - 1) {
            copyB(it + 1, (it + 1) & 1);
            asm volatile("cp.async.wait_group 1;" ::: "memory");
        } else {
            asm volatile("cp.async.wait_group 0;" ::: "memory");
        }
        __syncthreads();

        const uint32_t bHiB = bBase + (uint32_t)((it & 1) * BUFSZ);
        const uint32_t bLoB = bHiB + (uint32_t)BPL;

#pragma unroll
        for (int ks = 0; ks < BK / 16; ks++) {
            const uint32_t kb = ks * 32;
            uint32_t af[MT][4], bh[NTI][2], bl[NTI][2];
#pragma unroll
            for (int p = 0; p < NPAIR; p++)
                ldsm_x4(bh[2*p][0], bh[2*p][1], bh[2*p+1][0], bh[2*p+1][1],
                        bHiB + (uint32_t)(p * 16 * AST) + kb);
            if (NTI & 1)
                ldsm_x2(bh[NTI-1][0], bh[NTI-1][1],
                        bHiB + (uint32_t)((NTI-1) * 8 * AST) + kb);
#pragma unroll
            for (int mi = 0; mi < MT; mi++)
                ldsm_x4(af[mi][0], af[mi][1], af[mi][2], af[mi][3],
                        aHiB + (uint32_t)(mi * 16 * AST) + kb);
#pragma unroll
            for (int mi = 0; mi < MT; mi++)
#pragma unroll
                for (int ni = 0; ni < NTI; ni++)
                    mma_bf16(acc[mi][ni], af[mi], bh[ni]);
#pragma unroll
            for (int p = 0; p < NPAIR; p++)
                ldsm_x4(bl[2*p][0], bl[2*p][1], bl[2*p+1][0], bl[2*p+1][1],
                        bLoB + (uint32_t)(p * 16 * AST) + kb);
            if (NTI & 1)
                ldsm_x2(bl[NTI-1][0], bl[NTI-1][1],
                        bLoB + (uint32_t)((NTI-1) * 8 * AST) + kb);
#pragma unroll
            for (int mi = 0; mi < MT; mi++)
#pragma unroll
                for (int ni = 0; ni < NTI; ni++)
                    mma_bf16(acc[mi][ni], af[mi], bl[ni]);
#pragma unroll
            for (int mi = 0; mi < MT; mi++)
                ldsm_x4(af[mi][0], af[mi][1], af[mi][2], af[mi][3],
                        aLoB + (uint32_t)(mi * 16 * AST) + kb);
#pragma unroll
            for (int mi = 0; mi < MT; mi++)
#pragma unroll
                for (int ni = 0; ni < NTI; ni++)
                    mma_bf16(acc[mi][ni], af[mi], bh[ni]);
        }
        __syncthreads();
    }

    // ---- epilogue ----
#pragma unroll
    for (int mi = 0; mi < MT; mi++) {
        const int row0 = bm * BM + wmBase + mi * 16 + g;
#pragma unroll
        for (int ni = 0; ni < NTI; ni++) {
            const int col = nOff + wnBase + ni * 8 + c * 2;
            float2 bb = *reinterpret_cast<const float2*>(&bias[col]);
            float2 o0, o1;
            o0.x = acc[mi][ni][0] + bb.x;
            o0.y = acc[mi][ni][1] + bb.y;
            o1.x = acc[mi][ni][2] + bb.x;
            o1.y = acc[mi][ni][3] + bb.y;
            if constexpr (RES) {
                float2 r0 = *reinterpret_cast<const float2*>(&res[(size_t)row0 * ldC + col]);
                float2 r1 = *reinterpret_cast<const float2*>(&res[(size_t)(row0 + 8) * ldC + col]);
                o0.x += r0.x; o0.y += r0.y;
                o1.x += r1.x; o1.y += r1.y;
            }
            *reinterpret_cast<float2*>(&C[(size_t)row0 * ldC + col]) = o0;
            *reinterpret_cast<float2*>(&C[(size_t)(row0 + 8) * ldC + col]) = o1;
        }
    }
}

// ---------------- sampling: 2 heads per warp, float2 channel pairs ----------------
__global__ void __launch_bounds__(256)
sample_kernel(const float* __restrict__ refp, const float* __restrict__ oa,
              float* __restrict__ outp)
{
    const int lane  = threadIdx.x & 31;
    const int wid   = threadIdx.x >> 5;
    const int bq    = blockIdx.x * 2 + (wid >> 2);
    const int b     = bq / NQ;
    const int hPair = (wid & 3) * 2;
    const int half  = lane >> 4;
    const int h     = hPair + half;
    const int ch    = lane & 15;

    const float* oabase = oa + (size_t)bq * 96;

    float aw = 0.f, ox = 0.f, oy = 0.f;
    {
        const int hg = hPair + ((lane >> 2) & 1);
        const int p  = lane & 3;
        if (lane < 8) {
            aw = oabase[64 + hg * 4 + p];
            ox = oabase[hg * 8 + 2 * p];
            oy = oabase[hg * 8 + 2 * p + 1];
        }
    }
    float m = fmaxf(aw, __shfl_xor_sync(0xffffffffu, aw, 1));
    m = fmaxf(m, __shfl_xor_sync(0xffffffffu, m, 2));
    float e = __expf(aw - m);
    float s = e + __shfl_xor_sync(0xffffffffu, e, 1);
    s = s + __shfl_xor_sync(0xffffffffu, s, 2);
    const float wp = e / s;

    const float rx = refp[(size_t)bq * 2 + 0];
    const float ry = refp[(size_t)bq * 2 + 1];

    int   i00 = 0, i01 = 0, i10 = 0, i11 = 0;
    float w00 = 0.f, w01 = 0.f, w10 = 0.f, w11 = 0.f;
    {
        float locx = rx + ox * (1.f / (float)SW);
        float locy = ry + oy * (1.f / (float)SH);
        float gx = 2.f * locx - 1.f;
        float gy = 2.f * locy - 1.f;
        float px = ((gx + 1.f) * (float)SW - 1.f) * 0.5f;
        float py = ((gy + 1.f) * (float)SH - 1.f) * 0.5f;
        float x0f = floorf(px), y0f = floorf(py);
        int   x0 = (int)x0f,    y0 = (int)y0f;
        float fx = px - x0f,    fy = py - y0f;

        const bool xv0 = (x0 >= 0)     && (x0 <= SW - 1);
        const bool xv1 = (x0 + 1 >= 0) && (x0 + 1 <= SW - 1);
        const bool yv0 = (y0 >= 0)     && (y0 <= SH - 1);
        const bool yv1 = (y0 + 1 >= 0) && (y0 + 1 <= SH - 1);

        int xc0 = min(max(x0, 0), SW - 1);
        int xc1 = min(max(x0 + 1, 0), SW - 1);
        int yc0 = min(max(y0, 0), SH - 1);
        int yc1 = min(max(y0 + 1, 0), SH - 1);

        w00 = (xv0 && yv0) ? wp * (1.f - fx) * (1.f - fy) : 0.f;
        w01 = (xv1 && yv0) ? wp * fx * (1.f - fy)         : 0.f;
        w10 = (xv0 && yv1) ? wp * (1.f - fx) * fy         : 0.f;
        w11 = (xv1 && yv1) ? wp * fx * fy                 : 0.f;

        i00 = (yc0 * SW + xc0) * (EMBED / 2);
        i01 = (yc0 * SW + xc1) * (EMBED / 2);
        i10 = (yc1 * SW + xc0) * (EMBED / 2);
        i11 = (yc1 * SW + xc1) * (EMBED / 2);
    }

    const float2* vbase = reinterpret_cast<const float2*>(
        g_v + (size_t)b * NV * EMBED + h * HEAD_DIM) + ch;

    float2 acc; acc.x = 0.f; acc.y = 0.f;
#pragma unroll
    for (int p = 0; p < POINTS; p++) {
        const int src = half * 4 + p;
        const int   j00 = __shfl_sync(0xffffffffu, i00, src);
        const int   j01 = __shfl_sync(0xffffffffu, i01, src);
        const int   j10 = __shfl_sync(0xffffffffu, i10, src);
        const int   j11 = __shfl_sync(0xffffffffu, i11, src);
        const float u00 = __shfl_sync(0xffffffffu, w00, src);
        const float u01 = __shfl_sync(0xffffffffu, w01, src);
        const float u10 = __shfl_sync(0xffffffffu, w10, src);
        const float u11 = __shfl_sync(0xffffffffu, w11, src);
        float2 v00 = vbase[j00];
        float2 v01 = vbase[j01];
        float2 v10 = vbase[j10];
        float2 v11 = vbase[j11];
        acc.x = fmaf(u00, v00.x, acc.x); acc.y = fmaf(u00, v00.y, acc.y);
        acc.x = fmaf(u01, v01.x, acc.x); acc.y = fmaf(u01, v01.y, acc.y);
        acc.x = fmaf(u10, v10.x, acc.x); acc.y = fmaf(u10, v10.y, acc.y);
        acc.x = fmaf(u11, v11.x, acc.x); acc.y = fmaf(u11, v11.y, acc.y);
    }

    *reinterpret_cast<float2*>(&outp[(size_t)bq * EMBED + h * HEAD_DIM + ch * 2]) = acc;
}

// ---------------- launch ----------------
extern "C" void kernel_launch(void* const* d_in, const int* in_sizes, int n_in,
                              void* d_out, int out_size)
{
    const float* query   = (const float*)d_in[0];
    const float* value   = (const float*)d_in[1];
    const float* refpts  = (const float*)d_in[2];
    const float* W_value = (const float*)d_in[4];
    const float* b_value = (const float*)d_in[5];
    const float* W_off   = (const float*)d_in[6];
    const float* b_off   = (const float*)d_in[7];
    const float* W_attn  = (const float*)d_in[8];
    const float* b_attn  = (const float*)d_in[9];
    const float* W_out   = (const float*)d_in[10];
    const float* b_out   = (const float*)d_in[11];
    float* out = (float*)d_out;

    float *pv, *poa, *ptmp, *pboa;
    __nv_bfloat16 *wv_h, *wv_l, *wo_h, *wo_l, *woa_h, *woa_l;
    cudaGetSymbolAddress((void**)&pv,    g_v);
    cudaGetSymbolAddress((void**)&poa,   g_oa);
    cudaGetSymbolAddress((void**)&ptmp,  g_tmp);
    cudaGetSymbolAddress((void**)&pboa,  g_boa);
    cudaGetSymbolAddress((void**)&wv_h,  g_Wv_hi);  cudaGetSymbolAddress((void**)&wv_l,  g_Wv_lo);
    cudaGetSymbolAddress((void**)&wo_h,  g_Wo_hi);  cudaGetSymbolAddress((void**)&wo_l,  g_Wo_lo);
    cudaGetSymbolAddress((void**)&woa_h, g_Woa_hi); cudaGetSymbolAddress((void**)&woa_l, g_Woa_lo);

    // smem: A planes (2*128*144) + double-buffered B (2 * 2*BN*144)
    const int SMEM_128 = 2 * 128 * 144 + 2 * (2 * 128 * 144); // 110592
    const int SMEM_96  = 2 * 128 * 144 + 2 * (2 *  96 * 144); //  92160
    cudaFuncSetAttribute(mma_gemm_kernel<128, false>, cudaFuncAttributeMaxDynamicSharedMemorySize, SMEM_128);
    cudaFuncSetAttribute(mma_gemm_kernel<128, true >, cudaFuncAttributeMaxDynamicSharedMemorySize, SMEM_128);
    cudaFuncSetAttribute(mma_gemm_kernel< 96, false>, cudaFuncAttributeMaxDynamicSharedMemorySize, SMEM_96);

    // weight transpose + bf16 split
    convert_w_kernel<<<(256 * 256 + 255) / 256, 256>>>(W_value, wv_h, wv_l, 256);
    convert_w_kernel<<<(256 * 256 + 255) / 256, 256>>>(W_out,   wo_h, wo_l, 256);
    convert_oa_kernel<<<(96 * 256 + 255) / 256, 256>>>(W_off, b_off, W_attn, b_attn,
                                                       woa_h, woa_l, pboa);

    const int GRID = MROWS / 128; // 625

    // 1) v = value @ W_value + b_value       (N=256 split into 2x128)
    mma_gemm_kernel<128, false><<<dim3(GRID, 2), 256, SMEM_128>>>(
        value, wv_h, wv_l, b_value, nullptr, pv, 256);
    // 2+3) [off|attn] = query @ [W_off|W_attn] + bias   (N=96)
    mma_gemm_kernel<96, false><<<dim3(GRID, 1), 256, SMEM_96>>>(
        query, woa_h, woa_l, pboa, nullptr, poa, 96);
    // 4) softmax + bilinear sample (2 heads/warp, float2 channels)
    sample_kernel<<<MROWS / 2, 256>>>(refpts, poa, ptmp);
    // 5) out = tmp @ W_out + b_out + query   (N=256 split into 2x128)
    mma_gemm_kernel<128, true><<<dim3(GRID, 2), 256, SMEM_128>>>(
        ptmp, wo_h, wo_l, b_out, query, out, 256);
}

// round 10
// speedup vs baseline: 1.4948x; 1.4948x over previous
#include <cuda_runtime.h>
#include <cuda_fp16.h>
#include <math.h>
#include <stdint.h>

// ---------------- problem constants ----------------
#define BS      2
#define NQ      40000
#define NV      40000
#define EMBED   256
#define HEADS   8
#define POINTS  4
#define HEAD_DIM 32
#define SH      200
#define SW      200
#define MROWS   (BS * NQ)      // 80000

// ---------------- device scratch ----------------
__device__ float g_v   [(size_t)BS * NV * EMBED];        // projected value (fp32)
__device__ float g_oa  [(size_t)BS * NQ * 96];           // fused [off(64) | attn(32)]
__device__ float g_tmp [(size_t)BS * NQ * EMBED];
__device__ float g_boa [96];
// transposed weights: [N][K] fp16
__device__ __half g_Wv [256 * 256];
__device__ __half g_Wo [256 * 256];
__device__ __half g_Woa[ 96 * 256];

// ---------------- warp mma / ldmatrix helpers ----------------
__device__ __forceinline__ void mma_f16(float* d, const uint32_t* a, const uint32_t* b) {
    asm volatile(
        "mma.sync.aligned.m16n8k16.row.col.f32.f16.f16.f32 "
        "{%0,%1,%2,%3}, {%4,%5,%6,%7}, {%8,%9}, {%0,%1,%2,%3};"
        : "+f"(d[0]), "+f"(d[1]), "+f"(d[2]), "+f"(d[3])
        : "r"(a[0]), "r"(a[1]), "r"(a[2]), "r"(a[3]), "r"(b[0]), "r"(b[1]));
}
__device__ __forceinline__ void ldsm_x4(uint32_t& r0, uint32_t& r1, uint32_t& r2, uint32_t& r3,
                                        uint32_t addr) {
    asm volatile("ldmatrix.sync.aligned.m8n8.x4.shared.b16 {%0,%1,%2,%3}, [%4];"
                 : "=r"(r0), "=r"(r1), "=r"(r2), "=r"(r3) : "r"(addr));
}
__device__ __forceinline__ void ldsm_x2(uint32_t& r0, uint32_t& r1, uint32_t addr) {
    asm volatile("ldmatrix.sync.aligned.m8n8.x2.shared.b16 {%0,%1}, [%2];"
                 : "=r"(r0), "=r"(r1) : "r"(addr));
}
__device__ __forceinline__ uint32_t cvt_f16x2(float hi, float lo) {
    uint32_t r;
    asm("cvt.rn.f16x2.f32 %0, %1, %2;" : "=r"(r) : "f"(hi), "f"(lo));
    return r;
}

// ---------------- weight transpose to fp16 ----------------
__global__ void convert_w_kernel(const float* __restrict__ W,
                                 __half* __restrict__ Wt, int N)
{
    int idx = blockIdx.x * 256 + threadIdx.x;
    if (idx >= N * 256) return;
    int n = idx >> 8, k = idx & 255;
    Wt[idx] = __float2half_rn(W[k * N + n]);
}

// combined [W_off | W_attn] transpose, plus combined bias
__global__ void convert_oa_kernel(const float* __restrict__ Woff, const float* __restrict__ boff,
                                  const float* __restrict__ Wattn, const float* __restrict__ battn,
                                  __half* __restrict__ Wt, float* __restrict__ bcomb)
{
    int idx = blockIdx.x * 256 + threadIdx.x;
    if (idx >= 96 * 256) return;
    int n = idx >> 8, k = idx & 255;
    float v = (n < 64) ? Woff[k * 64 + n] : Wattn[k * 32 + (n - 64)];
    Wt[idx] = __float2half_rn(v);
    if (idx < 96) bcomb[idx] = (idx < 64) ? boff[idx] : battn[idx - 64];
}

// ---------------- fp16 HMMA GEMM: single pass, ldmatrix fragment loads ----------------
// CTA tile: 128 x BN. gridDim.y splits total N. 8 warps, warp tile 64 x (BN/4).
template<int BN, bool RES>
__global__ void __launch_bounds__(256, 2)
mma_gemm_kernel(const float* __restrict__ A,
                const __half* __restrict__ Bt,
                const float* __restrict__ bias,
                const float* __restrict__ res,
                float* __restrict__ C, int ldC)
{
    constexpr int K = 256, BK = 64, BM = 128;
    constexpr int WN  = 4;
    constexpr int WTN = BN / WN;           // 32 or 24 cols per warp
    constexpr int MT  = 4;                 // 64 rows per warp / 16
    constexpr int NTI = WTN / 8;           // 4 or 3
    constexpr int NPAIR = NTI / 2;
    constexpr int AST = 144;               // bytes per 64-fp16 row (128 + 16 pad)
    constexpr int A_0 = 0;
    constexpr int B_0 = BM * AST;

    extern __shared__ char sm[];
    const uint32_t smBase = (uint32_t)__cvta_generic_to_shared(sm);

    const int tid  = threadIdx.x;
    const int wid  = tid >> 5;
    const int lane = tid & 31;
    const int g    = lane >> 2;
    const int c    = lane & 3;
    const int wm   = wid / WN;
    const int wn   = wid % WN;
    const int wmBase = wm * 64;
    const int wnBase = wn * WTN;
    const int bm   = blockIdx.x;
    const int nOff = blockIdx.y * BN;

    float acc[MT][NTI][4];
#pragma unroll
    for (int i = 0; i < MT; i++)
#pragma unroll
        for (int j = 0; j < NTI; j++)
#pragma unroll
            for (int q = 0; q < 4; q++) acc[i][j][q] = 0.f;

    const int aRow = wmBase + (lane & 15);
    const int aKs  = (lane >> 4) * 16;
    const int bRow = wnBase + ((lane >> 4) << 3) + (lane & 7);
    const int bKs  = ((lane >> 3) & 1) * 16;
    const uint32_t aB = smBase + (uint32_t)(A_0 + aRow * AST + aKs);
    const uint32_t bB = smBase + (uint32_t)(B_0 + bRow * AST + bKs);

    for (int it = 0; it < K / BK; it++) {
        const int k0 = it * BK;
        // ---- fill A tile: 128 rows x 64 fp32 -> fp16 (packed cvt) ----
#pragma unroll
        for (int f = tid; f < BM * 16; f += 256) {
            const int r = f >> 4, c4 = f & 15;
            float4 a = *reinterpret_cast<const float4*>(
                &A[(size_t)(bm * BM + r) * K + k0 + c4 * 4]);
            uint2 v;
            v.x = cvt_f16x2(a.y, a.x);
            v.y = cvt_f16x2(a.w, a.z);
            *reinterpret_cast<uint2*>(sm + A_0 + r * AST + c4 * 8) = v;
        }
        // ---- fill B tile: BN rows x 64 fp16, 16B copies ----
#pragma unroll
        for (int f = tid; f < BN * 8; f += 256) {
            const int n = f >> 3, cu = f & 7;
            uint4 w = *reinterpret_cast<const uint4*>(&Bt[(nOff + n) * K + k0 + cu * 8]);
            *reinterpret_cast<uint4*>(sm + B_0 + n * AST + cu * 16) = w;
        }
        __syncthreads();

#pragma unroll
        for (int ks = 0; ks < BK / 16; ks++) {
            const uint32_t kb = ks * 32;
            uint32_t af[MT][4], bf[NTI][2];
#pragma unroll
            for (int p = 0; p < NPAIR; p++)
                ldsm_x4(bf[2*p][0], bf[2*p][1], bf[2*p+1][0], bf[2*p+1][1],
                        bB + (uint32_t)(p * 16 * AST) + kb);
            if (NTI & 1)
                ldsm_x2(bf[NTI-1][0], bf[NTI-1][1],
                        bB + (uint32_t)((NTI-1) * 8 * AST) + kb);
#pragma unroll
            for (int mi = 0; mi < MT; mi++)
                ldsm_x4(af[mi][0], af[mi][1], af[mi][2], af[mi][3],
                        aB + (uint32_t)(mi * 16 * AST) + kb);
#pragma unroll
            for (int mi = 0; mi < MT; mi++)
#pragma unroll
                for (int ni = 0; ni < NTI; ni++)
                    mma_f16(acc[mi][ni], af[mi], bf[ni]);
        }
        __syncthreads();
    }

    // ---- epilogue ----
#pragma unroll
    for (int mi = 0; mi < MT; mi++) {
        const int row0 = bm * BM + wmBase + mi * 16 + g;
#pragma unroll
        for (int ni = 0; ni < NTI; ni++) {
            const int col = nOff + wnBase + ni * 8 + c * 2;
            float2 bb = *reinterpret_cast<const float2*>(&bias[col]);
            float2 o0, o1;
            o0.x = acc[mi][ni][0] + bb.x;
            o0.y = acc[mi][ni][1] + bb.y;
            o1.x = acc[mi][ni][2] + bb.x;
            o1.y = acc[mi][ni][3] + bb.y;
            if constexpr (RES) {
                float2 r0 = *reinterpret_cast<const float2*>(&res[(size_t)row0 * ldC + col]);
                float2 r1 = *reinterpret_cast<const float2*>(&res[(size_t)(row0 + 8) * ldC + col]);
                o0.x += r0.x; o0.y += r0.y;
                o1.x += r1.x; o1.y += r1.y;
            }
            *reinterpret_cast<float2*>(&C[(size_t)row0 * ldC + col]) = o0;
            *reinterpret_cast<float2*>(&C[(size_t)(row0 + 8) * ldC + col]) = o1;
        }
    }
}

// ---------------- sampling: 2 heads per warp, float2 channel pairs ----------------
__global__ void __launch_bounds__(256)
sample_kernel(const float* __restrict__ refp, const float* __restrict__ oa,
              float* __restrict__ outp)
{
    const int lane  = threadIdx.x & 31;
    const int wid   = threadIdx.x >> 5;
    const int bq    = blockIdx.x * 2 + (wid >> 2);
    const int b     = bq / NQ;
    const int hPair = (wid & 3) * 2;
    const int half  = lane >> 4;
    const int h     = hPair + half;
    const int ch    = lane & 15;

    const float* oabase = oa + (size_t)bq * 96;

    float aw = 0.f, ox = 0.f, oy = 0.f;
    {
        const int hg = hPair + ((lane >> 2) & 1);
        const int p  = lane & 3;
        if (lane < 8) {
            aw = oabase[64 + hg * 4 + p];
            ox = oabase[hg * 8 + 2 * p];
            oy = oabase[hg * 8 + 2 * p + 1];
        }
    }
    float m = fmaxf(aw, __shfl_xor_sync(0xffffffffu, aw, 1));
    m = fmaxf(m, __shfl_xor_sync(0xffffffffu, m, 2));
    float e = __expf(aw - m);
    float s = e + __shfl_xor_sync(0xffffffffu, e, 1);
    s = s + __shfl_xor_sync(0xffffffffu, s, 2);
    const float wp = e / s;

    const float rx = refp[(size_t)bq * 2 + 0];
    const float ry = refp[(size_t)bq * 2 + 1];

    int   i00 = 0, i01 = 0, i10 = 0, i11 = 0;
    float w00 = 0.f, w01 = 0.f, w10 = 0.f, w11 = 0.f;
    {
        float locx = rx + ox * (1.f / (float)SW);
        float locy = ry + oy * (1.f / (float)SH);
        float gx = 2.f * locx - 1.f;
        float gy = 2.f * locy - 1.f;
        float px = ((gx + 1.f) * (float)SW - 1.f) * 0.5f;
        float py = ((gy + 1.f) * (float)SH - 1.f) * 0.5f;
        float x0f = floorf(px), y0f = floorf(py);
        int   x0 = (int)x0f,    y0 = (int)y0f;
        float fx = px - x0f,    fy = py - y0f;

        const bool xv0 = (x0 >= 0)     && (x0 <= SW - 1);
        const bool xv1 = (x0 + 1 >= 0) && (x0 + 1 <= SW - 1);
        const bool yv0 = (y0 >= 0)     && (y0 <= SH - 1);
        const bool yv1 = (y0 + 1 >= 0) && (y0 + 1 <= SH - 1);

        int xc0 = min(max(x0, 0), SW - 1);
        int xc1 = min(max(x0 + 1, 0), SW - 1);
        int yc0 = min(max(y0, 0), SH - 1);
        int yc1 = min(max(y0 + 1, 0), SH - 1);

        w00 = (xv0 && yv0) ? wp * (1.f - fx) * (1.f - fy) : 0.f;
        w01 = (xv1 && yv0) ? wp * fx * (1.f - fy)         : 0.f;
        w10 = (xv0 && yv1) ? wp * (1.f - fx) * fy         : 0.f;
        w11 = (xv1 && yv1) ? wp * fx * fy                 : 0.f;

        i00 = (yc0 * SW + xc0) * (EMBED / 2);
        i01 = (yc0 * SW + xc1) * (EMBED / 2);
        i10 = (yc1 * SW + xc0) * (EMBED / 2);
        i11 = (yc1 * SW + xc1) * (EMBED / 2);
    }

    const float2* vbase = reinterpret_cast<const float2*>(
        g_v + (size_t)b * NV * EMBED + h * HEAD_DIM) + ch;

    float2 acc; acc.x = 0.f; acc.y = 0.f;
#pragma unroll
    for (int p = 0; p < POINTS; p++) {
        const int src = half * 4 + p;
        const int   j00 = __shfl_sync(0xffffffffu, i00, src);
        const int   j01 = __shfl_sync(0xffffffffu, i01, src);
        const int   j10 = __shfl_sync(0xffffffffu, i10, src);
        const int   j11 = __shfl_sync(0xffffffffu, i11, src);
        const float u00 = __shfl_sync(0xffffffffu, w00, src);
        const float u01 = __shfl_sync(0xffffffffu, w01, src);
        const float u10 = __shfl_sync(0xffffffffu, w10, src);
        const float u11 = __shfl_sync(0xffffffffu, w11, src);
        float2 v00 = vbase[j00];
        float2 v01 = vbase[j01];
        float2 v10 = vbase[j10];
        float2 v11 = vbase[j11];
        acc.x = fmaf(u00, v00.x, acc.x); acc.y = fmaf(u00, v00.y, acc.y);
        acc.x = fmaf(u01, v01.x, acc.x); acc.y = fmaf(u01, v01.y, acc.y);
        acc.x = fmaf(u10, v10.x, acc.x); acc.y = fmaf(u10, v10.y, acc.y);
        acc.x = fmaf(u11, v11.x, acc.x); acc.y = fmaf(u11, v11.y, acc.y);
    }

    *reinterpret_cast<float2*>(&outp[(size_t)bq * EMBED + h * HEAD_DIM + ch * 2]) = acc;
}

// ---------------- launch ----------------
extern "C" void kernel_launch(void* const* d_in, const int* in_sizes, int n_in,
                              void* d_out, int out_size)
{
    const float* query   = (const float*)d_in[0];
    const float* value   = (const float*)d_in[1];
    const float* refpts  = (const float*)d_in[2];
    const float* W_value = (const float*)d_in[4];
    const float* b_value = (const float*)d_in[5];
    const float* W_off   = (const float*)d_in[6];
    const float* b_off   = (const float*)d_in[7];
    const float* W_attn  = (const float*)d_in[8];
    const float* b_attn  = (const float*)d_in[9];
    const float* W_out   = (const float*)d_in[10];
    const float* b_out   = (const float*)d_in[11];
    float* out = (float*)d_out;

    float *pv, *poa, *ptmp, *pboa;
    __half *wv, *wo, *woa;
    cudaGetSymbolAddress((void**)&pv,   g_v);
    cudaGetSymbolAddress((void**)&poa,  g_oa);
    cudaGetSymbolAddress((void**)&ptmp, g_tmp);
    cudaGetSymbolAddress((void**)&pboa, g_boa);
    cudaGetSymbolAddress((void**)&wv,   g_Wv);
    cudaGetSymbolAddress((void**)&wo,   g_Wo);
    cudaGetSymbolAddress((void**)&woa,  g_Woa);

    // smem: A plane (128*144) + B plane (BN*144)
    const int SMEM_128 = (128 + 128) * 144; // 36864
    const int SMEM_96  = (128 +  96) * 144; // 32256
    cudaFuncSetAttribute(mma_gemm_kernel<128, false>, cudaFuncAttributeMaxDynamicSharedMemorySize, SMEM_128);
    cudaFuncSetAttribute(mma_gemm_kernel<128, true >, cudaFuncAttributeMaxDynamicSharedMemorySize, SMEM_128);
    cudaFuncSetAttribute(mma_gemm_kernel< 96, false>, cudaFuncAttributeMaxDynamicSharedMemorySize, SMEM_96);

    // weight transpose to fp16
    convert_w_kernel<<<(256 * 256 + 255) / 256, 256>>>(W_value, wv, 256);
    convert_w_kernel<<<(256 * 256 + 255) / 256, 256>>>(W_out,   wo, 256);
    convert_oa_kernel<<<(96 * 256 + 255) / 256, 256>>>(W_off, b_off, W_attn, b_attn, woa, pboa);

    const int GRID = MROWS / 128; // 625

    // 1) v = value @ W_value + b_value       (N=256 split into 2x128)
    mma_gemm_kernel<128, false><<<dim3(GRID, 2), 256, SMEM_128>>>(
        value, wv, b_value, nullptr, pv, 256);
    // 2+3) [off|attn] = query @ [W_off|W_attn] + bias   (N=96)
    mma_gemm_kernel<96, false><<<dim3(GRID, 1), 256, SMEM_96>>>(
        query, woa, pboa, nullptr, poa, 96);
    // 4) softmax + bilinear sample (2 heads/warp, float2 channels)
    sample_kernel<<<MROWS / 2, 256>>>(refpts, poa, ptmp);
    // 5) out = tmp @ W_out + b_out + query   (N=256 split into 2x128)
    mma_gemm_kernel<128, true><<<dim3(GRID, 2), 256, SMEM_128>>>(
        ptmp, wo, b_out, query, out, 256);
}

// round 11
// speedup vs baseline: 1.5795x; 1.0567x over previous
#include <cuda_runtime.h>
#include <cuda_fp16.h>
#include <math.h>
#include <stdint.h>

// ---------------- problem constants ----------------
#define BS      2
#define NQ      40000
#define NV      40000
#define EMBED   256
#define HEADS   8
#define POINTS  4
#define HEAD_DIM 32
#define SH      200
#define SW      200
#define MROWS   (BS * NQ)      // 80000

// ---------------- device scratch ----------------
__device__ float g_v   [(size_t)BS * NV * EMBED];        // projected value (fp32)
__device__ float g_oa  [(size_t)BS * NQ * 96];           // fused [off(64) | attn(32)]
__device__ float g_tmp [(size_t)BS * NQ * EMBED];
__device__ float g_boa [96];
// transposed weights: [N][K] fp16
__device__ __half g_Wv [256 * 256];
__device__ __half g_Wo [256 * 256];
__device__ __half g_Woa[ 96 * 256];

// ---------------- warp mma / ldmatrix helpers ----------------
__device__ __forceinline__ void mma_f16(float* d, const uint32_t* a, const uint32_t* b) {
    asm volatile(
        "mma.sync.aligned.m16n8k16.row.col.f32.f16.f16.f32 "
        "{%0,%1,%2,%3}, {%4,%5,%6,%7}, {%8,%9}, {%0,%1,%2,%3};"
        : "+f"(d[0]), "+f"(d[1]), "+f"(d[2]), "+f"(d[3])
        : "r"(a[0]), "r"(a[1]), "r"(a[2]), "r"(a[3]), "r"(b[0]), "r"(b[1]));
}
__device__ __forceinline__ void ldsm_x4(uint32_t& r0, uint32_t& r1, uint32_t& r2, uint32_t& r3,
                                        uint32_t addr) {
    asm volatile("ldmatrix.sync.aligned.m8n8.x4.shared.b16 {%0,%1,%2,%3}, [%4];"
                 : "=r"(r0), "=r"(r1), "=r"(r2), "=r"(r3) : "r"(addr));
}
__device__ __forceinline__ void ldsm_x2(uint32_t& r0, uint32_t& r1, uint32_t addr) {
    asm volatile("ldmatrix.sync.aligned.m8n8.x2.shared.b16 {%0,%1}, [%2];"
                 : "=r"(r0), "=r"(r1) : "r"(addr));
}
__device__ __forceinline__ uint32_t cvt_f16x2(float hi, float lo) {
    uint32_t r;
    asm("cvt.rn.f16x2.f32 %0, %1, %2;" : "=r"(r) : "f"(hi), "f"(lo));
    return r;
}

// ---------------- weight transpose to fp16 ----------------
__global__ void convert_w_kernel(const float* __restrict__ W,
                                 __half* __restrict__ Wt, int N)
{
    int idx = blockIdx.x * 256 + threadIdx.x;
    if (idx >= N * 256) return;
    int n = idx >> 8, k = idx & 255;
    Wt[idx] = __float2half_rn(W[k * N + n]);
}

__global__ void convert_oa_kernel(const float* __restrict__ Woff, const float* __restrict__ boff,
                                  const float* __restrict__ Wattn, const float* __restrict__ battn,
                                  __half* __restrict__ Wt, float* __restrict__ bcomb)
{
    int idx = blockIdx.x * 256 + threadIdx.x;
    if (idx >= 96 * 256) return;
    int n = idx >> 8, k = idx & 255;
    float v = (n < 64) ? Woff[k * 64 + n] : Wattn[k * 32 + (n - 64)];
    Wt[idx] = __float2half_rn(v);
    if (idx < 96) bcomb[idx] = (idx < 64) ? boff[idx] : battn[idx - 64];
}

// ---------------- fp16 HMMA GEMM: single pass, ldmatrix fragment loads ----------------
// CTA tile: 128 x BN. N-split is the FAST grid dim (blockIdx.x) so the two
// CTAs of a row-block co-schedule and share the A tile via L2.
template<int BN, bool RES>
__global__ void __launch_bounds__(256, 2)
mma_gemm_kernel(const float* __restrict__ A,
                const __half* __restrict__ Bt,
                const float* __restrict__ bias,
                const float* __restrict__ res,
                float* __restrict__ C, int ldC)
{
    constexpr int K = 256, BK = 64, BM = 128;
    constexpr int WN  = 4;
    constexpr int WTN = BN / WN;
    constexpr int MT  = 4;
    constexpr int NTI = WTN / 8;
    constexpr int NPAIR = NTI / 2;
    constexpr int AST = 144;
    constexpr int A_0 = 0;
    constexpr int B_0 = BM * AST;

    extern __shared__ char sm[];
    const uint32_t smBase = (uint32_t)__cvta_generic_to_shared(sm);

    const int tid  = threadIdx.x;
    const int wid  = tid >> 5;
    const int lane = tid & 31;
    const int g    = lane >> 2;
    const int c    = lane & 3;
    const int wm   = wid / WN;
    const int wn   = wid % WN;
    const int wmBase = wm * 64;
    const int wnBase = wn * WTN;
    const int bm   = blockIdx.y;
    const int nOff = blockIdx.x * BN;

    float acc[MT][NTI][4];
#pragma unroll
    for (int i = 0; i < MT; i++)
#pragma unroll
        for (int j = 0; j < NTI; j++)
#pragma unroll
            for (int q = 0; q < 4; q++) acc[i][j][q] = 0.f;

    const int aRow = wmBase + (lane & 15);
    const int aKs  = (lane >> 4) * 16;
    const int bRow = wnBase + ((lane >> 4) << 3) + (lane & 7);
    const int bKs  = ((lane >> 3) & 1) * 16;
    const uint32_t aB = smBase + (uint32_t)(A_0 + aRow * AST + aKs);
    const uint32_t bB = smBase + (uint32_t)(B_0 + bRow * AST + bKs);

    for (int it = 0; it < K / BK; it++) {
        const int k0 = it * BK;
        // ---- fill A tile: 128 rows x 64 fp32 -> fp16 (packed cvt) ----
#pragma unroll
        for (int f = tid; f < BM * 16; f += 256) {
            const int r = f >> 4, c4 = f & 15;
            float4 a = *reinterpret_cast<const float4*>(
                &A[(size_t)(bm * BM + r) * K + k0 + c4 * 4]);
            uint2 v;
            v.x = cvt_f16x2(a.y, a.x);
            v.y = cvt_f16x2(a.w, a.z);
            *reinterpret_cast<uint2*>(sm + A_0 + r * AST + c4 * 8) = v;
        }
        // ---- fill B tile: BN rows x 64 fp16, 16B copies ----
#pragma unroll
        for (int f = tid; f < BN * 8; f += 256) {
            const int n = f >> 3, cu = f & 7;
            uint4 w = *reinterpret_cast<const uint4*>(&Bt[(nOff + n) * K + k0 + cu * 8]);
            *reinterpret_cast<uint4*>(sm + B_0 + n * AST + cu * 16) = w;
        }
        __syncthreads();

#pragma unroll
        for (int ks = 0; ks < BK / 16; ks++) {
            const uint32_t kb = ks * 32;
            uint32_t af[MT][4], bf[NTI][2];
#pragma unroll
            for (int p = 0; p < NPAIR; p++)
                ldsm_x4(bf[2*p][0], bf[2*p][1], bf[2*p+1][0], bf[2*p+1][1],
                        bB + (uint32_t)(p * 16 * AST) + kb);
            if (NTI & 1)
                ldsm_x2(bf[NTI-1][0], bf[NTI-1][1],
                        bB + (uint32_t)((NTI-1) * 8 * AST) + kb);
#pragma unroll
            for (int mi = 0; mi < MT; mi++)
                ldsm_x4(af[mi][0], af[mi][1], af[mi][2], af[mi][3],
                        aB + (uint32_t)(mi * 16 * AST) + kb);
#pragma unroll
            for (int mi = 0; mi < MT; mi++)
#pragma unroll
                for (int ni = 0; ni < NTI; ni++)
                    mma_f16(acc[mi][ni], af[mi], bf[ni]);
        }
        __syncthreads();
    }

    // ---- epilogue ----
#pragma unroll
    for (int mi = 0; mi < MT; mi++) {
        const int row0 = bm * BM + wmBase + mi * 16 + g;
#pragma unroll
        for (int ni = 0; ni < NTI; ni++) {
            const int col = nOff + wnBase + ni * 8 + c * 2;
            float2 bb = *reinterpret_cast<const float2*>(&bias[col]);
            float2 o0, o1;
            o0.x = acc[mi][ni][0] + bb.x;
            o0.y = acc[mi][ni][1] + bb.y;
            o1.x = acc[mi][ni][2] + bb.x;
            o1.y = acc[mi][ni][3] + bb.y;
            if constexpr (RES) {
                float2 r0 = *reinterpret_cast<const float2*>(&res[(size_t)row0 * ldC + col]);
                float2 r1 = *reinterpret_cast<const float2*>(&res[(size_t)(row0 + 8) * ldC + col]);
                o0.x += r0.x; o0.y += r0.y;
                o1.x += r1.x; o1.y += r1.y;
            }
            *reinterpret_cast<float2*>(&C[(size_t)row0 * ldC + col]) = o0;
            *reinterpret_cast<float2*>(&C[(size_t)(row0 + 8) * ldC + col]) = o1;
        }
    }
}

// ---------------- sampling v4: 4 heads per warp, float4 channels ----------------
// Block = 256 threads = 8 warps, handles 4 queries (warp pair per query).
// Warp: head group hG = (wid&1)*4; lane group = lane>>3 selects head hG+group;
// lane&7 selects float4 channel quad. Geometry for 16 (head,point) pairs lives
// on lanes 0-15 (quad per head), broadcast via variable-source shfl.
__global__ void __launch_bounds__(256)
sample_kernel(const float* __restrict__ refp, const float* __restrict__ oa,
              float* __restrict__ outp)
{
    const int lane  = threadIdx.x & 31;
    const int wid   = threadIdx.x >> 5;
    const int bq    = blockIdx.x * 4 + (wid >> 1);
    const int b     = bq / NQ;
    const int hG    = (wid & 1) * 4;
    const int group = lane >> 3;            // 0..3 -> head hG+group
    const int h     = hG + group;
    const int ch4   = lane & 7;             // float4 channel index

    const float* oabase = oa + (size_t)bq * 96;

    // lanes 0..15: geometry for (head hG + (lane>>2), point lane&3)
    float aw = 0.f, ox = 0.f, oy = 0.f;
    {
        const int hg = hG + (lane >> 2);
        const int p  = lane & 3;
        if (lane < 16) {
            aw = oabase[64 + hg * 4 + p];
            ox = oabase[hg * 8 + 2 * p];
            oy = oabase[hg * 8 + 2 * p + 1];
        }
    }
    // softmax within each quad
    float m = fmaxf(aw, __shfl_xor_sync(0xffffffffu, aw, 1));
    m = fmaxf(m, __shfl_xor_sync(0xffffffffu, m, 2));
    float e = __expf(aw - m);
    float s = e + __shfl_xor_sync(0xffffffffu, e, 1);
    s = s + __shfl_xor_sync(0xffffffffu, s, 2);
    const float wp = e / s;                 // valid on lanes 0..15

    const float rx = refp[(size_t)bq * 2 + 0];
    const float ry = refp[(size_t)bq * 2 + 1];

    int   i00 = 0, i01 = 0, i10 = 0, i11 = 0;   // float4-unit offsets
    float w00 = 0.f, w01 = 0.f, w10 = 0.f, w11 = 0.f;
    {
        float locx = rx + ox * (1.f / (float)SW);
        float locy = ry + oy * (1.f / (float)SH);
        float gx = 2.f * locx - 1.f;
        float gy = 2.f * locy - 1.f;
        float px = ((gx + 1.f) * (float)SW - 1.f) * 0.5f;
        float py = ((gy + 1.f) * (float)SH - 1.f) * 0.5f;
        float x0f = floorf(px), y0f = floorf(py);
        int   x0 = (int)x0f,    y0 = (int)y0f;
        float fx = px - x0f,    fy = py - y0f;

        const bool xv0 = (x0 >= 0)     && (x0 <= SW - 1);
        const bool xv1 = (x0 + 1 >= 0) && (x0 + 1 <= SW - 1);
        const bool yv0 = (y0 >= 0)     && (y0 <= SH - 1);
        const bool yv1 = (y0 + 1 >= 0) && (y0 + 1 <= SH - 1);

        int xc0 = min(max(x0, 0), SW - 1);
        int xc1 = min(max(x0 + 1, 0), SW - 1);
        int yc0 = min(max(y0, 0), SH - 1);
        int yc1 = min(max(y0 + 1, 0), SH - 1);

        w00 = (xv0 && yv0) ? wp * (1.f - fx) * (1.f - fy) : 0.f;
        w01 = (xv1 && yv0) ? wp * fx * (1.f - fy)         : 0.f;
        w10 = (xv0 && yv1) ? wp * (1.f - fx) * fy         : 0.f;
        w11 = (xv1 && yv1) ? wp * fx * fy                 : 0.f;

        i00 = (yc0 * SW + xc0) * (EMBED / 4);
        i01 = (yc0 * SW + xc1) * (EMBED / 4);
        i10 = (yc1 * SW + xc0) * (EMBED / 4);
        i11 = (yc1 * SW + xc1) * (EMBED / 4);
    }

    const float4* vbase = reinterpret_cast<const float4*>(
        g_v + (size_t)b * NV * EMBED + h * HEAD_DIM) + ch4;

    float4 acc; acc.x = 0.f; acc.y = 0.f; acc.z = 0.f; acc.w = 0.f;
#pragma unroll
    for (int p = 0; p < POINTS; p++) {
        const int src = group * 4 + p;      // geometry lane for this head's point p
        const int   j00 = __shfl_sync(0xffffffffu, i00, src);
        const int   j01 = __shfl_sync(0xffffffffu, i01, src);
        const int   j10 = __shfl_sync(0xffffffffu, i10, src);
        const int   j11 = __shfl_sync(0xffffffffu, i11, src);
        const float u00 = __shfl_sync(0xffffffffu, w00, src);
        const float u01 = __shfl_sync(0xffffffffu, w01, src);
        const float u10 = __shfl_sync(0xffffffffu, w10, src);
        const float u11 = __shfl_sync(0xffffffffu, w11, src);
        float4 v00 = vbase[j00];
        float4 v01 = vbase[j01];
        float4 v10 = vbase[j10];
        float4 v11 = vbase[j11];
        acc.x = fmaf(u00, v00.x, acc.x); acc.y = fmaf(u00, v00.y, acc.y);
        acc.z = fmaf(u00, v00.z, acc.z); acc.w = fmaf(u00, v00.w, acc.w);
        acc.x = fmaf(u01, v01.x, acc.x); acc.y = fmaf(u01, v01.y, acc.y);
        acc.z = fmaf(u01, v01.z, acc.z); acc.w = fmaf(u01, v01.w, acc.w);
        acc.x = fmaf(u10, v10.x, acc.x); acc.y = fmaf(u10, v10.y, acc.y);
        acc.z = fmaf(u10, v10.z, acc.z); acc.w = fmaf(u10, v10.w, acc.w);
        acc.x = fmaf(u11, v11.x, acc.x); acc.y = fmaf(u11, v11.y, acc.y);
        acc.z = fmaf(u11, v11.z, acc.z); acc.w = fmaf(u11, v11.w, acc.w);
    }

    *reinterpret_cast<float4*>(&outp[(size_t)bq * EMBED + h * HEAD_DIM + ch4 * 4]) = acc;
}

// ---------------- launch ----------------
extern "C" void kernel_launch(void* const* d_in, const int* in_sizes, int n_in,
                              void* d_out, int out_size)
{
    const float* query   = (const float*)d_in[0];
    const float* value   = (const float*)d_in[1];
    const float* refpts  = (const float*)d_in[2];
    const float* W_value = (const float*)d_in[4];
    const float* b_value = (const float*)d_in[5];
    const float* W_off   = (const float*)d_in[6];
    const float* b_off   = (const float*)d_in[7];
    const float* W_attn  = (const float*)d_in[8];
    const float* b_attn  = (const float*)d_in[9];
    const float* W_out   = (const float*)d_in[10];
    const float* b_out   = (const float*)d_in[11];
    float* out = (float*)d_out;

    float *pv, *poa, *ptmp, *pboa;
    __half *wv, *wo, *woa;
    cudaGetSymbolAddress((void**)&pv,   g_v);
    cudaGetSymbolAddress((void**)&poa,  g_oa);
    cudaGetSymbolAddress((void**)&ptmp, g_tmp);
    cudaGetSymbolAddress((void**)&pboa, g_boa);
    cudaGetSymbolAddress((void**)&wv,   g_Wv);
    cudaGetSymbolAddress((void**)&wo,   g_Wo);
    cudaGetSymbolAddress((void**)&woa,  g_Woa);

    const int SMEM_128 = (128 + 128) * 144; // 36864
    const int SMEM_96  = (128 +  96) * 144; // 32256
    cudaFuncSetAttribute(mma_gemm_kernel<128, false>, cudaFuncAttributeMaxDynamicSharedMemorySize, SMEM_128);
    cudaFuncSetAttribute(mma_gemm_kernel<128, true >, cudaFuncAttributeMaxDynamicSharedMemorySize, SMEM_128);
    cudaFuncSetAttribute(mma_gemm_kernel< 96, false>, cudaFuncAttributeMaxDynamicSharedMemorySize, SMEM_96);

    // weight transpose to fp16
    convert_w_kernel<<<(256 * 256 + 255) / 256, 256>>>(W_value, wv, 256);
    convert_w_kernel<<<(256 * 256 + 255) / 256, 256>>>(W_out,   wo, 256);
    convert_oa_kernel<<<(96 * 256 + 255) / 256, 256>>>(W_off, b_off, W_attn, b_attn, woa, pboa);

    const int GRID = MROWS / 128; // 625

    // 1) v = value @ W_value + b_value       (N split fast-dim: grid (2, 625))
    mma_gemm_kernel<128, false><<<dim3(2, GRID), 256, SMEM_128>>>(
        value, wv, b_value, nullptr, pv, 256);
    // 2+3) [off|attn] = query @ [W_off|W_attn] + bias   (N=96)
    mma_gemm_kernel<96, false><<<dim3(1, GRID), 256, SMEM_96>>>(
        query, woa, pboa, nullptr, poa, 96);
    // 4) softmax + bilinear sample (4 heads/warp, float4 channels)
    sample_kernel<<<MROWS / 4, 256>>>(refpts, poa, ptmp);
    // 5) out = tmp @ W_out + b_out + query   (N split fast-dim)
    mma_gemm_kernel<128, true><<<dim3(2, GRID), 256, SMEM_128>>>(
        ptmp, wo, b_out, query, out, 256);
}

// round 12
// speedup vs baseline: 1.7072x; 1.0808x over previous
#include <cuda_runtime.h>
#include <cuda_fp16.h>
#include <math.h>
#include <stdint.h>

// ---------------- problem constants ----------------
#define BS      2
#define NQ      40000
#define NV      40000
#define EMBED   256
#define HEADS   8
#define POINTS  4
#define HEAD_DIM 32
#define SH      200
#define SW      200
#define MROWS   (BS * NQ)      // 80000

// ---------------- device scratch ----------------
__device__ float  g_v   [(size_t)BS * NV * EMBED];       // projected value (fp32)
__device__ float  g_oa  [(size_t)BS * NQ * 96];          // fused [off(64) | attn(32)]
__device__ __half g_tmp [(size_t)BS * NQ * EMBED];       // sampled output (fp16)
__device__ float  g_boa [96];
// transposed weights: [N][K] fp16
__device__ __half g_Wv [256 * 256];
__device__ __half g_Wo [256 * 256];
__device__ __half g_Woa[ 96 * 256];

// ---------------- warp mma / ldmatrix helpers ----------------
__device__ __forceinline__ void mma_f16(float* d, const uint32_t* a, const uint32_t* b) {
    asm volatile(
        "mma.sync.aligned.m16n8k16.row.col.f32.f16.f16.f32 "
        "{%0,%1,%2,%3}, {%4,%5,%6,%7}, {%8,%9}, {%0,%1,%2,%3};"
        : "+f"(d[0]), "+f"(d[1]), "+f"(d[2]), "+f"(d[3])
        : "r"(a[0]), "r"(a[1]), "r"(a[2]), "r"(a[3]), "r"(b[0]), "r"(b[1]));
}
__device__ __forceinline__ void ldsm_x4(uint32_t& r0, uint32_t& r1, uint32_t& r2, uint32_t& r3,
                                        uint32_t addr) {
    asm volatile("ldmatrix.sync.aligned.m8n8.x4.shared.b16 {%0,%1,%2,%3}, [%4];"
                 : "=r"(r0), "=r"(r1), "=r"(r2), "=r"(r3) : "r"(addr));
}
__device__ __forceinline__ void ldsm_x2(uint32_t& r0, uint32_t& r1, uint32_t addr) {
    asm volatile("ldmatrix.sync.aligned.m8n8.x2.shared.b16 {%0,%1}, [%2];"
                 : "=r"(r0), "=r"(r1) : "r"(addr));
}
__device__ __forceinline__ uint32_t cvt_f16x2(float hi, float lo) {
    uint32_t r;
    asm("cvt.rn.f16x2.f32 %0, %1, %2;" : "=r"(r) : "f"(hi), "f"(lo));
    return r;
}

// ---------------- merged weight transpose to fp16 ----------------
// region 0: W_value [256x256] -> g_Wv; region 1: W_out -> g_Wo; region 2: [W_off|W_attn] -> g_Woa
__global__ void convert_all_kernel(const float* __restrict__ Wv, const float* __restrict__ Wo,
                                   const float* __restrict__ Woff, const float* __restrict__ boff,
                                   const float* __restrict__ Wattn, const float* __restrict__ battn,
                                   __half* __restrict__ dWv, __half* __restrict__ dWo,
                                   __half* __restrict__ dWoa, float* __restrict__ bcomb)
{
    int idx = blockIdx.x * 256 + threadIdx.x;
    if (idx < 65536) {
        int n = idx >> 8, k = idx & 255;
        dWv[idx] = __float2half_rn(Wv[k * 256 + n]);
    } else if (idx < 131072) {
        int j = idx - 65536;
        int n = j >> 8, k = j & 255;
        dWo[j] = __float2half_rn(Wo[k * 256 + n]);
    } else if (idx < 131072 + 24576) {
        int j = idx - 131072;
        int n = j >> 8, k = j & 255;
        float v = (n < 64) ? Woff[k * 64 + n] : Wattn[k * 32 + (n - 64)];
        dWoa[j] = __float2half_rn(v);
        if (j < 96) bcomb[j] = (j < 64) ? boff[j] : battn[j - 64];
    }
}

// ---------------- fp16 HMMA GEMM: single pass, BK=128, ldmatrix loads ----------------
// CTA tile: 128 x BN. N-split fast grid dim (blockIdx.x). AT = float (cvt fill) or __half (copy).
template<int BN, bool RES, typename AT>
__global__ void __launch_bounds__(256, 2)
mma_gemm_kernel(const AT* __restrict__ A,
                const __half* __restrict__ Bt,
                const float* __restrict__ bias,
                const float* __restrict__ res,
                float* __restrict__ C, int ldC)
{
    constexpr int K = 256, BK = 128, BM = 128;
    constexpr int WN  = 4;
    constexpr int WTN = BN / WN;
    constexpr int MT  = 4;
    constexpr int NTI = WTN / 8;
    constexpr int NPAIR = NTI / 2;
    constexpr int AST = 272;               // bytes per 128-fp16 row (256 + 16 pad)
    constexpr int A_0 = 0;
    constexpr int B_0 = BM * AST;

    extern __shared__ char sm[];
    const uint32_t smBase = (uint32_t)__cvta_generic_to_shared(sm);

    const int tid  = threadIdx.x;
    const int wid  = tid >> 5;
    const int lane = tid & 31;
    const int g    = lane >> 2;
    const int c    = lane & 3;
    const int wm   = wid / WN;
    const int wn   = wid % WN;
    const int wmBase = wm * 64;
    const int wnBase = wn * WTN;
    const int bm   = blockIdx.y;
    const int nOff = blockIdx.x * BN;

    float acc[MT][NTI][4];
#pragma unroll
    for (int i = 0; i < MT; i++)
#pragma unroll
        for (int j = 0; j < NTI; j++)
#pragma unroll
            for (int q = 0; q < 4; q++) acc[i][j][q] = 0.f;

    const int aRow = wmBase + (lane & 15);
    const int aKs  = (lane >> 4) * 16;
    const int bRow = wnBase + ((lane >> 4) << 3) + (lane & 7);
    const int bKs  = ((lane >> 3) & 1) * 16;
    const uint32_t aB = smBase + (uint32_t)(A_0 + aRow * AST + aKs);
    const uint32_t bB = smBase + (uint32_t)(B_0 + bRow * AST + bKs);

    for (int it = 0; it < K / BK; it++) {
        const int k0 = it * BK;
        // ---- fill A tile: 128 rows x 128 cols ----
        if constexpr (sizeof(AT) == 4) {
            // fp32 -> fp16 with packed cvt: 32 float4 per row
#pragma unroll
            for (int f = tid; f < BM * 32; f += 256) {
                const int r = f >> 5, c4 = f & 31;
                float4 a = *reinterpret_cast<const float4*>(
                    &A[(size_t)(bm * BM + r) * K + k0 + c4 * 4]);
                uint2 v;
                v.x = cvt_f16x2(a.y, a.x);
                v.y = cvt_f16x2(a.w, a.z);
                *reinterpret_cast<uint2*>(sm + A_0 + r * AST + c4 * 8) = v;
            }
        } else {
            // fp16 pure 16B copies: 16 uint4 per row
#pragma unroll
            for (int f = tid; f < BM * 16; f += 256) {
                const int r = f >> 4, cu = f & 15;
                uint4 w = *reinterpret_cast<const uint4*>(
                    &A[(size_t)(bm * BM + r) * K + k0 + cu * 8]);
                *reinterpret_cast<uint4*>(sm + A_0 + r * AST + cu * 16) = w;
            }
        }
        // ---- fill B tile: BN rows x 128 fp16, 16B copies ----
#pragma unroll
        for (int f = tid; f < BN * 16; f += 256) {
            const int n = f >> 4, cu = f & 15;
            uint4 w = *reinterpret_cast<const uint4*>(&Bt[(nOff + n) * K + k0 + cu * 8]);
            *reinterpret_cast<uint4*>(sm + B_0 + n * AST + cu * 16) = w;
        }
        __syncthreads();

#pragma unroll
        for (int ks = 0; ks < BK / 16; ks++) {
            const uint32_t kb = ks * 32;
            uint32_t af[MT][4], bf[NTI][2];
#pragma unroll
            for (int p = 0; p < NPAIR; p++)
                ldsm_x4(bf[2*p][0], bf[2*p][1], bf[2*p+1][0], bf[2*p+1][1],
                        bB + (uint32_t)(p * 16 * AST) + kb);
            if (NTI & 1)
                ldsm_x2(bf[NTI-1][0], bf[NTI-1][1],
                        bB + (uint32_t)((NTI-1) * 8 * AST) + kb);
#pragma unroll
            for (int mi = 0; mi < MT; mi++)
                ldsm_x4(af[mi][0], af[mi][1], af[mi][2], af[mi][3],
                        aB + (uint32_t)(mi * 16 * AST) + kb);
#pragma unroll
            for (int mi = 0; mi < MT; mi++)
#pragma unroll
                for (int ni = 0; ni < NTI; ni++)
                    mma_f16(acc[mi][ni], af[mi], bf[ni]);
        }
        __syncthreads();
    }

    // ---- epilogue ----
#pragma unroll
    for (int mi = 0; mi < MT; mi++) {
        const int row0 = bm * BM + wmBase + mi * 16 + g;
#pragma unroll
        for (int ni = 0; ni < NTI; ni++) {
            const int col = nOff + wnBase + ni * 8 + c * 2;
            float2 bb = *reinterpret_cast<const float2*>(&bias[col]);
            float2 o0, o1;
            o0.x = acc[mi][ni][0] + bb.x;
            o0.y = acc[mi][ni][1] + bb.y;
            o1.x = acc[mi][ni][2] + bb.x;
            o1.y = acc[mi][ni][3] + bb.y;
            if constexpr (RES) {
                float2 r0 = *reinterpret_cast<const float2*>(&res[(size_t)row0 * ldC + col]);
                float2 r1 = *reinterpret_cast<const float2*>(&res[(size_t)(row0 + 8) * ldC + col]);
                o0.x += r0.x; o0.y += r0.y;
                o1.x += r1.x; o1.y += r1.y;
            }
            *reinterpret_cast<float2*>(&C[(size_t)row0 * ldC + col]) = o0;
            *reinterpret_cast<float2*>(&C[(size_t)(row0 + 8) * ldC + col]) = o1;
        }
    }
}

// ---------------- sampling: 4 heads per warp, float4 channels, fp16 out ----------------
__global__ void __launch_bounds__(256)
sample_kernel(const float* __restrict__ refp, const float* __restrict__ oa,
              __half* __restrict__ outp)
{
    const int lane  = threadIdx.x & 31;
    const int wid   = threadIdx.x >> 5;
    const int bq    = blockIdx.x * 4 + (wid >> 1);
    const int b     = bq / NQ;
    const int hG    = (wid & 1) * 4;
    const int group = lane >> 3;
    const int h     = hG + group;
    const int ch4   = lane & 7;

    const float* oabase = oa + (size_t)bq * 96;

    float aw = 0.f, ox = 0.f, oy = 0.f;
    {
        const int hg = hG + (lane >> 2);
        const int p  = lane & 3;
        if (lane < 16) {
            aw = oabase[64 + hg * 4 + p];
            ox = oabase[hg * 8 + 2 * p];
            oy = oabase[hg * 8 + 2 * p + 1];
        }
    }
    float m = fmaxf(aw, __shfl_xor_sync(0xffffffffu, aw, 1));
    m = fmaxf(m, __shfl_xor_sync(0xffffffffu, m, 2));
    float e = __expf(aw - m);
    float s = e + __shfl_xor_sync(0xffffffffu, e, 1);
    s = s + __shfl_xor_sync(0xffffffffu, s, 2);
    const float wp = e / s;

    const float rx = refp[(size_t)bq * 2 + 0];
    const float ry = refp[(size_t)bq * 2 + 1];

    int   i00 = 0, i01 = 0, i10 = 0, i11 = 0;
    float w00 = 0.f, w01 = 0.f, w10 = 0.f, w11 = 0.f;
    {
        float locx = rx + ox * (1.f / (float)SW);
        float locy = ry + oy * (1.f / (float)SH);
        float gx = 2.f * locx - 1.f;
        float gy = 2.f * locy - 1.f;
        float px = ((gx + 1.f) * (float)SW - 1.f) * 0.5f;
        float py = ((gy + 1.f) * (float)SH - 1.f) * 0.5f;
        float x0f = floorf(px), y0f = floorf(py);
        int   x0 = (int)x0f,    y0 = (int)y0f;
        float fx = px - x0f,    fy = py - y0f;

        const bool xv0 = (x0 >= 0)     && (x0 <= SW - 1);
        const bool xv1 = (x0 + 1 >= 0) && (x0 + 1 <= SW - 1);
        const bool yv0 = (y0 >= 0)     && (y0 <= SH - 1);
        const bool yv1 = (y0 + 1 >= 0) && (y0 + 1 <= SH - 1);

        int xc0 = min(max(x0, 0), SW - 1);
        int xc1 = min(max(x0 + 1, 0), SW - 1);
        int yc0 = min(max(y0, 0), SH - 1);
        int yc1 = min(max(y0 + 1, 0), SH - 1);

        w00 = (xv0 && yv0) ? wp * (1.f - fx) * (1.f - fy) : 0.f;
        w01 = (xv1 && yv0) ? wp * fx * (1.f - fy)         : 0.f;
        w10 = (xv0 && yv1) ? wp * (1.f - fx) * fy         : 0.f;
        w11 = (xv1 && yv1) ? wp * fx * fy                 : 0.f;

        i00 = (yc0 * SW + xc0) * (EMBED / 4);
        i01 = (yc0 * SW + xc1) * (EMBED / 4);
        i10 = (yc1 * SW + xc0) * (EMBED / 4);
        i11 = (yc1 * SW + xc1) * (EMBED / 4);
    }

    const float4* vbase = reinterpret_cast<const float4*>(
        g_v + (size_t)b * NV * EMBED + h * HEAD_DIM) + ch4;

    float4 acc; acc.x = 0.f; acc.y = 0.f; acc.z = 0.f; acc.w = 0.f;
#pragma unroll
    for (int p = 0; p < POINTS; p++) {
        const int src = group * 4 + p;
        const int   j00 = __shfl_sync(0xffffffffu, i00, src);
        const int   j01 = __shfl_sync(0xffffffffu, i01, src);
        const int   j10 = __shfl_sync(0xffffffffu, i10, src);
        const int   j11 = __shfl_sync(0xffffffffu, i11, src);
        const float u00 = __shfl_sync(0xffffffffu, w00, src);
        const float u01 = __shfl_sync(0xffffffffu, w01, src);
        const float u10 = __shfl_sync(0xffffffffu, w10, src);
        const float u11 = __shfl_sync(0xffffffffu, w11, src);
        float4 v00 = vbase[j00];
        float4 v01 = vbase[j01];
        float4 v10 = vbase[j10];
        float4 v11 = vbase[j11];
        acc.x = fmaf(u00, v00.x, acc.x); acc.y = fmaf(u00, v00.y, acc.y);
        acc.z = fmaf(u00, v00.z, acc.z); acc.w = fmaf(u00, v00.w, acc.w);
        acc.x = fmaf(u01, v01.x, acc.x); acc.y = fmaf(u01, v01.y, acc.y);
        acc.z = fmaf(u01, v01.z, acc.z); acc.w = fmaf(u01, v01.w, acc.w);
        acc.x = fmaf(u10, v10.x, acc.x); acc.y = fmaf(u10, v10.y, acc.y);
        acc.z = fmaf(u10, v10.z, acc.z); acc.w = fmaf(u10, v10.w, acc.w);
        acc.x = fmaf(u11, v11.x, acc.x); acc.y = fmaf(u11, v11.y, acc.y);
        acc.z = fmaf(u11, v11.z, acc.z); acc.w = fmaf(u11, v11.w, acc.w);
    }

    // pack to fp16 (same rounding gemm3's fill would apply) and store 8B
    uint2 pk;
    pk.x = cvt_f16x2(acc.y, acc.x);
    pk.y = cvt_f16x2(acc.w, acc.z);
    *reinterpret_cast<uint2*>(&outp[(size_t)bq * EMBED + h * HEAD_DIM + ch4 * 4]) = pk;
}

// ---------------- launch ----------------
extern "C" void kernel_launch(void* const* d_in, const int* in_sizes, int n_in,
                              void* d_out, int out_size)
{
    const float* query   = (const float*)d_in[0];
    const float* value   = (const float*)d_in[1];
    const float* refpts  = (const float*)d_in[2];
    const float* W_value = (const float*)d_in[4];
    const float* b_value = (const float*)d_in[5];
    const float* W_off   = (const float*)d_in[6];
    const float* b_off   = (const float*)d_in[7];
    const float* W_attn  = (const float*)d_in[8];
    const float* b_attn  = (const float*)d_in[9];
    const float* W_out   = (const float*)d_in[10];
    const float* b_out   = (const float*)d_in[11];
    float* out = (float*)d_out;

    float *pv, *poa, *pboa;
    __half *ptmp, *wv, *wo, *woa;
    cudaGetSymbolAddress((void**)&pv,   g_v);
    cudaGetSymbolAddress((void**)&poa,  g_oa);
    cudaGetSymbolAddress((void**)&ptmp, g_tmp);
    cudaGetSymbolAddress((void**)&pboa, g_boa);
    cudaGetSymbolAddress((void**)&wv,   g_Wv);
    cudaGetSymbolAddress((void**)&wo,   g_Wo);
    cudaGetSymbolAddress((void**)&woa,  g_Woa);

    const int SMEM_128 = (128 + 128) * 272; // 69632
    const int SMEM_96  = (128 +  96) * 272; // 60928
    cudaFuncSetAttribute(mma_gemm_kernel<128, false, float >, cudaFuncAttributeMaxDynamicSharedMemorySize, SMEM_128);
    cudaFuncSetAttribute(mma_gemm_kernel<128, true,  __half>, cudaFuncAttributeMaxDynamicSharedMemorySize, SMEM_128);
    cudaFuncSetAttribute(mma_gemm_kernel< 96, false, float >, cudaFuncAttributeMaxDynamicSharedMemorySize, SMEM_96);

    // merged weight transpose to fp16
    convert_all_kernel<<<(131072 + 24576 + 255) / 256, 256>>>(
        W_value, W_out, W_off, b_off, W_attn, b_attn, wv, wo, woa, pboa);

    const int GRID = MROWS / 128; // 625

    // 1) v = value @ W_value + b_value       (N split fast-dim)
    mma_gemm_kernel<128, false, float><<<dim3(2, GRID), 256, SMEM_128>>>(
        value, wv, b_value, nullptr, pv, 256);
    // 2+3) [off|attn] = query @ [W_off|W_attn] + bias   (N=96)
    mma_gemm_kernel<96, false, float><<<dim3(1, GRID), 256, SMEM_96>>>(
        query, woa, pboa, nullptr, poa, 96);
    // 4) softmax + bilinear sample -> fp16 tmp
    sample_kernel<<<MROWS / 4, 256>>>(refpts, poa, ptmp);
    // 5) out = tmp(fp16) @ W_out + b_out + query
    mma_gemm_kernel<128, true, __half><<<dim3(2, GRID), 256, SMEM_128>>>(
        ptmp, wo, b_out, query, out, 256);
}